// round 12
// baseline (speedup 1.0000x reference)
#include <cuda_runtime.h>
#include <cuda_fp16.h>
#include <math.h>
#include <stdint.h>

// ---------------------------------------------------------------------------
// LiveNet fused forward (sm_100 plain target; fp16 mma.sync + ldmatrix).
//   K0 : convert [W21;Wobs1] -> g_wh (fp16)                 [1024,1024]
//   K1 : h = relu(x @ W1^T + b1) via mma -> g_h (fp16), converting x/W1
//        fp32->fp16 inline                                  [32768,1024]
//   K2 : persistent fp16 GEMM h @ g_wh^T (BK=32, 4-stage), fused relu +
//        layer-3 partial dots -> g_part; LAST tile per m-block runs the
//        CBF epilogue in-kernel (atomic counter) -> out [32768,14]
// ---------------------------------------------------------------------------

#define B_ROWS 32768
#define NUM_IN 20
#define H1     1024

__device__ __half g_h  [(size_t)B_ROWS * H1];
__device__ __half g_wh [(size_t)1024 * H1];
__device__ float  g_part[(size_t)B_ROWS * 16];
__device__ int    g_cnt[256];   // zero-init; reset to 0 by last arrival

// ---------------------------------------------------------------------------
// Kernel 0: layer-2 weight conversion. grid 1024, block 256.
// ---------------------------------------------------------------------------
__global__ __launch_bounds__(256) void k0_convert(
    const float* __restrict__ W21, const float* __restrict__ Wobs1)
{
    const size_t i4 = ((size_t)blockIdx.x * 256 + threadIdx.x) * 4;
    const size_t half_total = (size_t)512 * H1;
    const float* src = (i4 < half_total) ? (W21 + i4) : (Wobs1 + (i4 - half_total));
    float4 v = *(const float4*)src;
    __half2* dst = (__half2*)&g_wh[i4];
    dst[0] = __floats2half2_rn(v.x, v.y);
    dst[1] = __floats2half2_rn(v.z, v.w);
}

// ---------------------------------------------------------------------------
// helpers
// ---------------------------------------------------------------------------
__device__ __forceinline__ void mma16(float* c, const uint32_t* a, const uint32_t* b) {
    asm volatile(
        "mma.sync.aligned.m16n8k16.row.col.f32.f16.f16.f32 "
        "{%0,%1,%2,%3}, {%4,%5,%6,%7}, {%8,%9}, {%0,%1,%2,%3};"
        : "+f"(c[0]), "+f"(c[1]), "+f"(c[2]), "+f"(c[3])
        : "r"(a[0]), "r"(a[1]), "r"(a[2]), "r"(a[3]), "r"(b[0]), "r"(b[1]));
}

__device__ __forceinline__ void ldmx4(uint32_t* r, uint32_t addr) {
    asm volatile("ldmatrix.sync.aligned.m8n8.x4.shared.b16 {%0,%1,%2,%3}, [%4];"
                 : "=r"(r[0]), "=r"(r[1]), "=r"(r[2]), "=r"(r[3]) : "r"(addr));
}

__device__ __forceinline__ void cpa_cg(uint32_t d, const __half* s) {
    asm volatile("cp.async.cg.shared.global [%0], [%1], 16;" :: "r"(d), "l"(s));
}
__device__ __forceinline__ void cpa_ca(uint32_t d, const __half* s) {
    asm volatile("cp.async.ca.shared.global [%0], [%1], 16;" :: "r"(d), "l"(s));
}

// ---------------------------------------------------------------------------
// Kernel 1: layer-1 via mma, inline fp32->fp16 conversion of x and W1.
// BM=128, BN=128, K=32 (20 real + 12 zero). grid (8, 256), block 256.
// ---------------------------------------------------------------------------
#define K1_SSTR 40

__global__ __launch_bounds__(256) void k1_mma(
    const float* __restrict__ x, const float* __restrict__ W1,
    const float* __restrict__ b1)
{
    __shared__ __half xa[128 * K1_SSTR];
    __shared__ __half wb[128 * K1_SSTR];
    __shared__ float  bs[128];

    const int tid  = threadIdx.x;
    const int wid  = tid >> 5;
    const int lane = tid & 31;
    const int g    = lane >> 2;
    const int t    = lane & 3;
    const int wm   = (wid & 3) * 32;
    const int wn   = (wid >> 2) * 64;

    const int m0 = blockIdx.y * 128;
    const int n0 = blockIdx.x * 128;

    // zero-fill both tiles (covers pad cols 20..31)
    {
        const uint4 z = make_uint4(0, 0, 0, 0);
        for (int i = tid; i < (128 * K1_SSTR) / 8; i += 256) {
            ((uint4*)xa)[i] = z;
            ((uint4*)wb)[i] = z;
        }
    }
    __syncthreads();

    // scatter-convert x and W1 rows (fp32 -> fp16)
    for (int i = tid; i < 128 * NUM_IN; i += 256) {
        const int r = i / NUM_IN, c = i % NUM_IN;
        xa[r * K1_SSTR + c] = __float2half_rn(x[(size_t)(m0 + r) * NUM_IN + c]);
        wb[r * K1_SSTR + c] = __float2half_rn(W1[(size_t)(n0 + r) * NUM_IN + c]);
    }
    if (tid < 128) bs[tid] = b1[n0 + tid];
    __syncthreads();

    float acc[2][8][4];
#pragma unroll
    for (int mt = 0; mt < 2; mt++)
#pragma unroll
        for (int nt = 0; nt < 8; nt++)
#pragma unroll
            for (int j = 0; j < 4; j++) acc[mt][nt][j] = 0.0f;

#pragma unroll
    for (int ks = 0; ks < 2; ks++) {
        const int kc = ks * 16 + 2 * t;
        uint32_t af[2][4];
#pragma unroll
        for (int mt = 0; mt < 2; mt++) {
            const __half* ap = xa + (wm + mt * 16 + g) * K1_SSTR + kc;
            af[mt][0] = *(const uint32_t*)(ap);
            af[mt][1] = *(const uint32_t*)(ap + 8 * K1_SSTR);
            af[mt][2] = *(const uint32_t*)(ap + 8);
            af[mt][3] = *(const uint32_t*)(ap + 8 * K1_SSTR + 8);
        }
#pragma unroll
        for (int nt = 0; nt < 8; nt++) {
            const __half* bp = wb + (wn + nt * 8 + g) * K1_SSTR + kc;
            uint32_t bf[2];
            bf[0] = *(const uint32_t*)(bp);
            bf[1] = *(const uint32_t*)(bp + 8);
            mma16(acc[0][nt], af[0], bf);
            mma16(acc[1][nt], af[1], bf);
        }
    }

#pragma unroll
    for (int nt = 0; nt < 8; nt++) {
        const int col = wn + nt * 8 + t * 2;
        const float b0 = bs[col], b1v = bs[col + 1];
#pragma unroll
        for (int q = 0; q < 4; q++) {
            const int mt = q >> 1, h = q & 1;
            const int row = m0 + wm + mt * 16 + h * 8 + g;
            const float v0 = fmaxf(acc[mt][nt][h * 2 + 0] + b0, 0.0f);
            const float v1 = fmaxf(acc[mt][nt][h * 2 + 1] + b1v, 0.0f);
            *(__half2*)&g_h[(size_t)row * H1 + n0 + col] = __floats2half2_rn(v0, v1);
        }
    }
}

// ---------------------------------------------------------------------------
// Kernel 2: persistent fp16 mma GEMM + fused CBF final epilogue.
// BM=128, BN=128, BK=32, 4-stage cp.async. grid 296, block 256.
// ---------------------------------------------------------------------------
#define SSTRH    40
#define TILE_H   (128 * SSTRH)
#define STAGE_H  (2 * TILE_H)
#define STAGE_B  (STAGE_H * 2)
#define TILE_B   (TILE_H * 2)
#define K2_SMEM_BYTES (4 * STAGE_B)
#define NTILES   2048
#define K2_GRID  296

__global__ __launch_bounds__(256, 2) void k2_mma(
    const float* __restrict__ b21,   const float* __restrict__ bobs1,
    const float* __restrict__ W31,   const float* __restrict__ Wobs2,
    const float* __restrict__ x,
    const float* __restrict__ mean_, const float* __restrict__ stdv,
    const float* __restrict__ pb31,  const float* __restrict__ pbobs2,
    float* __restrict__ out)
{
    extern __shared__ __half smh[];
    __shared__ float ws[2][128];
    __shared__ float sred[2][128][2];
    __shared__ int   s_last;

    const int tid  = threadIdx.x;
    const int wid  = tid >> 5;
    const int lane = tid & 31;
    const int g    = lane >> 2;
    const int t    = lane & 3;
    const int wm   = (wid & 3) * 32;
    const int wn   = (wid >> 2) * 64;
    const int half = wid >> 2;

    uint32_t smem_base;
    asm("{ .reg .u64 t; cvta.to.shared.u64 t, %1; cvt.u32.u64 %0, t; }"
        : "=r"(smem_base) : "l"(smh));

    const int lm = tid >> 2;
    const int lq = tid & 3;
    const uint32_t dOff = (uint32_t)(lm * SSTRH * 2 + lq * 16);

    const int lr  = lane & 7;
    const int sel = lane >> 3;
    uint32_t aOffL[2];
#pragma unroll
    for (int mt = 0; mt < 2; mt++)
        aOffL[mt] = (uint32_t)(((wm + mt * 16 + lr + (sel & 1) * 8) * SSTRH
                               + (sel >> 1) * 8) * 2);
    uint32_t bOffL[4];
#pragma unroll
    for (int np = 0; np < 4; np++)
        bOffL[np] = (uint32_t)(TILE_B + ((wn + np * 16 + lr + (sel >> 1) * 8) * SSTRH
                               + (sel & 1) * 8) * 2);

    for (int tile = blockIdx.x; tile < NTILES; tile += K2_GRID) {
        const int mb = tile >> 3;
        const int m0 = mb * 128;
        const int n0 = (tile & 7) * 128;
        const int pair = (n0 >= 512);

        const float* bsrc = pair ? (bobs1 + (n0 - 512)) : (b21 + n0);
        const float* w0g  = pair ? (Wobs2 + (n0 - 512)) : (W31 + n0);
        const float* w1g  = pair ? (Wobs2 + 512 + (n0 - 512)) : (W31 + 512 + n0);

        const __half* aG = &g_h [(size_t)(m0 + lm) * H1 + lq * 8];
        const __half* bG = &g_wh[(size_t)(n0 + lm) * H1 + lq * 8];

        float acc[2][8][4];
#pragma unroll
        for (int mt = 0; mt < 2; mt++)
#pragma unroll
            for (int nt = 0; nt < 8; nt++)
#pragma unroll
                for (int j = 0; j < 4; j++) acc[mt][nt][j] = 0.0f;

        // ---- prologue: stages 0..2 ----
#pragma unroll
        for (int p = 0; p < 3; p++) {
            const uint32_t aB = smem_base + p * STAGE_B + dOff;
            const uint32_t bB = aB + (uint32_t)TILE_B;
            const int k0 = p * 32;
#pragma unroll
            for (int i = 0; i < 2; i++) {
                cpa_cg(aB + i * 64 * SSTRH * 2, aG + (size_t)i * 64 * H1 + k0);
                cpa_ca(bB + i * 64 * SSTRH * 2, bG + (size_t)i * 64 * H1 + k0);
            }
            asm volatile("cp.async.commit_group;");
        }

        // ---- 32 slabs of BK=32 ----
        for (int s = 0; s < 32; s++) {
            const int stg = s & 3;
            asm volatile("cp.async.wait_group 2;");
            __syncthreads();

            if (s + 3 < 32) {
                const int pst = (s + 3) & 3;
                const uint32_t aB = smem_base + pst * STAGE_B + dOff;
                const uint32_t bB = aB + (uint32_t)TILE_B;
                const int k0 = (s + 3) * 32;
#pragma unroll
                for (int i = 0; i < 2; i++) {
                    cpa_cg(aB + i * 64 * SSTRH * 2, aG + (size_t)i * 64 * H1 + k0);
                    cpa_ca(bB + i * 64 * SSTRH * 2, bG + (size_t)i * 64 * H1 + k0);
                }
            }
            asm volatile("cp.async.commit_group;");

            {
                const uint32_t tb = smem_base + stg * STAGE_B;
#pragma unroll
                for (int ks = 0; ks < 2; ks++) {
                    const uint32_t kb = tb + ks * 32;
                    uint32_t af[2][4];
                    ldmx4(af[0], kb + aOffL[0]);
                    ldmx4(af[1], kb + aOffL[1]);
#pragma unroll
                    for (int np = 0; np < 4; np++) {
                        uint32_t bf[4];
                        ldmx4(bf, kb + bOffL[np]);
                        mma16(acc[0][2 * np + 0], af[0], bf);
                        mma16(acc[0][2 * np + 1], af[0], bf + 2);
                        mma16(acc[1][2 * np + 0], af[1], bf);
                        mma16(acc[1][2 * np + 1], af[1], bf + 2);
                    }
                }
            }
        }

        // ---- epilogue: relu + partial layer-3 dots ----
        if (tid < 128) ws[0][tid] = w0g[tid];
        else           ws[1][tid - 128] = w1g[tid - 128];
        __syncthreads();

        float u[4][2];
#pragma unroll
        for (int q = 0; q < 4; q++) { u[q][0] = 0.0f; u[q][1] = 0.0f; }

#pragma unroll
        for (int nt = 0; nt < 8; nt++) {
            const int col = wn + nt * 8 + t * 2;
            const float2 bb = *(const float2*)&bsrc[col];
            const float wa0 = ws[0][col], wa1 = ws[0][col + 1];
            const float wb0 = ws[1][col], wb1 = ws[1][col + 1];
#pragma unroll
            for (int q = 0; q < 4; q++) {
                const int mt = q >> 1, h = q & 1;
                const float v0 = fmaxf(acc[mt][nt][h * 2 + 0] + bb.x, 0.0f);
                const float v1 = fmaxf(acc[mt][nt][h * 2 + 1] + bb.y, 0.0f);
                u[q][0] = fmaf(v0, wa0, fmaf(v1, wa1, u[q][0]));
                u[q][1] = fmaf(v0, wb0, fmaf(v1, wb1, u[q][1]));
            }
        }

#pragma unroll
        for (int q = 0; q < 4; q++)
#pragma unroll
            for (int c = 0; c < 2; c++) {
                u[q][c] += __shfl_xor_sync(0xFFFFFFFFu, u[q][c], 1);
                u[q][c] += __shfl_xor_sync(0xFFFFFFFFu, u[q][c], 2);
            }

        if (t == 0) {
#pragma unroll
            for (int q = 0; q < 4; q++) {
                const int row = wm + (q >> 1) * 16 + (q & 1) * 8 + g;
                sred[half][row][0] = u[q][0];
                sred[half][row][1] = u[q][1];
            }
        }
        __syncthreads();

        {
            const int row = tid >> 1;
            const int c   = tid & 1;
            const float sum = sred[0][row][c] + sred[1][row][c];
            const int nb4 = tile & 3;
            g_part[(size_t)(m0 + row) * 16 + pair * 8 + nb4 * 2 + c] = sum;
        }

        // ---- completion count: last of 8 tiles runs the CBF epilogue ----
        __threadfence();
        __syncthreads();
        if (tid == 0) s_last = (atomicAdd(&g_cnt[mb], 1) == 7) ? 1 : 0;
        __syncthreads();

        if (s_last) {
            __threadfence();   // acquire: see all 8 tiles' g_part writes
            if (tid < 128) {
                const int row = m0 + tid;
                const float* pp = &g_part[(size_t)row * 16];
                float4 pa = *(const float4*)&pp[0];
                float4 pb = *(const float4*)&pp[4];
                float4 pc = *(const float4*)&pp[8];
                float4 pd = *(const float4*)&pp[12];

                const float x31_0 = pa.x + pa.z + pb.x + pb.z + pb31[0];
                const float x31_1 = pa.y + pa.w + pb.y + pb.w + pb31[1];
                const float t0    = pc.x + pc.z + pd.x + pd.z + pbobs2[0];
                const float t1    = pc.y + pc.w + pd.y + pd.w + pbobs2[1];
                const float p0 = 4.0f / (1.0f + expf(-t0));
                const float p1 = 4.0f / (1.0f + expf(-t1));

                const float* xr = x + (size_t)row * NUM_IN;
                float x0v[NUM_IN];
#pragma unroll
                for (int c = 2; c < NUM_IN; c++)
                    x0v[c] = fmaf(xr[c], stdv[c], mean_[c]);

                const float theta = x0v[2];
                const float v     = x0v[3];
                const float st = sinf(theta), ct = cosf(theta);
                const float ox = x0v[4], oy = x0v[5], oth = x0v[6], ov = x0v[7];
                const float dx = -ox, dy = -oy;
                const float ost = sinf(oth), oct = cosf(oth);
                const float R2 = 0.45f * 0.45f;

                const float barrier = dx * dx + dy * dy - R2;
                const float bdot    = 2.0f * dx * (v * ct - ov * oct)
                                    + 2.0f * dy * (v * st - ov * ost);
                const float Lf2b    = 2.0f * (v * v + ov * ov
                                    - 2.0f * v * ov * cosf(theta + oth));
                const float Gu1 = -2.0f * dx * v * st + 2.0f * dy * v * ct;
                const float Gu2 =  2.0f * dx * ct + 2.0f * dy * st;

                const float psum  = p0 + p1;
                const float pprod = p0 * p1;

                float o[14];
                o[0]  = x31_0;
                o[1]  = x31_1;
                o[2]  = -Gu1;
                o[3]  = -Gu2;
                o[10] = Lf2b + psum * bdot + pprod * barrier;

                const float sLf2b = 2.0f * v * v;
#pragma unroll
                for (int j = 0; j < 3; j++) {
                    const float sdx = -x0v[8 + 4 * j];
                    const float sdy = -x0v[9 + 4 * j];
                    const float sb    = sdx * sdx + sdy * sdy - R2;
                    const float sbdot = 2.0f * sdx * v * ct + 2.0f * sdy * v * st;
                    const float sGu1  = -2.0f * sdx * v * st + 2.0f * sdy * v * ct;
                    const float sGu2  =  2.0f * sdx * ct + 2.0f * sdy * st;
                    o[4 + 2 * j] = -sGu1;
                    o[5 + 2 * j] = -sGu2;
                    o[11 + j]    = sLf2b + psum * sbdot + pprod * sb;
                }

                float* op = out + (size_t)row * 14;
#pragma unroll
                for (int i = 0; i < 14; i++) op[i] = o[i];
            }
            if (tid == 0) g_cnt[mb] = 0;   // reset for next graph replay
        }
        __syncthreads();
    }
}

// ---------------------------------------------------------------------------
// Launch
// ---------------------------------------------------------------------------
extern "C" void kernel_launch(void* const* d_in, const int* in_sizes, int n_in,
                              void* d_out, int out_size)
{
    const float* x      = (const float*)d_in[0];
    const float* mean_  = (const float*)d_in[2];
    const float* stdv   = (const float*)d_in[3];
    const float* W1     = (const float*)d_in[4];
    const float* b1     = (const float*)d_in[5];
    const float* W21    = (const float*)d_in[6];
    const float* b21    = (const float*)d_in[7];
    const float* W31    = (const float*)d_in[8];
    const float* b31    = (const float*)d_in[9];
    const float* Wobs1  = (const float*)d_in[10];
    const float* bobs1  = (const float*)d_in[11];
    const float* Wobs2  = (const float*)d_in[12];
    const float* bobs2  = (const float*)d_in[13];
    float* out = (float*)d_out;

    cudaFuncSetAttribute(k2_mma, cudaFuncAttributeMaxDynamicSharedMemorySize,
                         K2_SMEM_BYTES);

    k0_convert<<<1024, 256>>>(W21, Wobs1);
    k1_mma<<<dim3(8, B_ROWS / 128), 256>>>(x, W1, b1);
    k2_mma<<<K2_GRID, 256, K2_SMEM_BYTES>>>(b21, bobs1, W31, Wobs2,
                                            x, mean_, stdv, b31, bobs2, out);
}

// round 13
// speedup vs baseline: 1.0226x; 1.0226x over previous
#include <cuda_runtime.h>
#include <cuda_fp16.h>
#include <math.h>
#include <stdint.h>

// ---------------------------------------------------------------------------
// LiveNet fused forward (sm_100 plain target; fp16 mma.sync + ldmatrix).
//   K01: blocks 0..2047  -> layer-1 mma tiles (inline fp32->fp16 of x/W1)
//        blocks 2048..3071 -> [W21;Wobs1] fp32->fp16 conversion (overlapped)
//   K2 : persistent fp16 GEMM h @ g_wh^T (BK=32, 4-stage), fused relu +
//        layer-3 partial dots -> g_part
//   K3 : sum partials, sigmoid, CBF epilogue -> out [32768,14]
// ---------------------------------------------------------------------------

#define B_ROWS 32768
#define NUM_IN 20
#define H1     1024

__device__ __half g_h  [(size_t)B_ROWS * H1];
__device__ __half g_wh [(size_t)1024 * H1];
__device__ float  g_part[(size_t)B_ROWS * 16];

// ---------------------------------------------------------------------------
// helpers
// ---------------------------------------------------------------------------
__device__ __forceinline__ void mma16(float* c, const uint32_t* a, const uint32_t* b) {
    asm volatile(
        "mma.sync.aligned.m16n8k16.row.col.f32.f16.f16.f32 "
        "{%0,%1,%2,%3}, {%4,%5,%6,%7}, {%8,%9}, {%0,%1,%2,%3};"
        : "+f"(c[0]), "+f"(c[1]), "+f"(c[2]), "+f"(c[3])
        : "r"(a[0]), "r"(a[1]), "r"(a[2]), "r"(a[3]), "r"(b[0]), "r"(b[1]));
}

__device__ __forceinline__ void ldmx4(uint32_t* r, uint32_t addr) {
    asm volatile("ldmatrix.sync.aligned.m8n8.x4.shared.b16 {%0,%1,%2,%3}, [%4];"
                 : "=r"(r[0]), "=r"(r[1]), "=r"(r[2]), "=r"(r[3]) : "r"(addr));
}

__device__ __forceinline__ void cpa_cg(uint32_t d, const __half* s) {
    asm volatile("cp.async.cg.shared.global [%0], [%1], 16;" :: "r"(d), "l"(s));
}
__device__ __forceinline__ void cpa_ca(uint32_t d, const __half* s) {
    asm volatile("cp.async.ca.shared.global [%0], [%1], 16;" :: "r"(d), "l"(s));
}

// ---------------------------------------------------------------------------
// Kernel 01: layer-1 mma tiles + overlapped weight conversion.
// grid 3072 (1D), block 256.
// ---------------------------------------------------------------------------
#define K1_SSTR 40

__global__ __launch_bounds__(256) void k01_l1_and_convert(
    const float* __restrict__ x,   const float* __restrict__ W1,
    const float* __restrict__ b1,
    const float* __restrict__ W21, const float* __restrict__ Wobs1)
{
    const int tid = threadIdx.x;

    if (blockIdx.x >= 2048) {
        // ---- weight conversion: [W21;Wobs1] -> g_wh (fp16) ----
        const size_t i4 = ((size_t)(blockIdx.x - 2048) * 256 + tid) * 4;
        const size_t half_total = (size_t)512 * H1;
        const float* src = (i4 < half_total) ? (W21 + i4) : (Wobs1 + (i4 - half_total));
        float4 v = *(const float4*)src;
        __half2* dst = (__half2*)&g_wh[i4];
        dst[0] = __floats2half2_rn(v.x, v.y);
        dst[1] = __floats2half2_rn(v.z, v.w);
        return;
    }

    // ---- layer-1 mma tile ----
    __shared__ __half xa[128 * K1_SSTR];
    __shared__ __half wb[128 * K1_SSTR];
    __shared__ float  bs[128];

    const int wid  = tid >> 5;
    const int lane = tid & 31;
    const int g    = lane >> 2;
    const int t    = lane & 3;
    const int wm   = (wid & 3) * 32;
    const int wn   = (wid >> 2) * 64;

    const int m0 = (blockIdx.x >> 3) * 128;
    const int n0 = (blockIdx.x & 7) * 128;

    // zero-fill both tiles (covers pad cols 20..31)
    {
        const uint4 z = make_uint4(0, 0, 0, 0);
        for (int i = tid; i < (128 * K1_SSTR) / 8; i += 256) {
            ((uint4*)xa)[i] = z;
            ((uint4*)wb)[i] = z;
        }
    }
    __syncthreads();

    // scatter-convert x and W1 rows (fp32 -> fp16)
    for (int i = tid; i < 128 * NUM_IN; i += 256) {
        const int r = i / NUM_IN, c = i % NUM_IN;
        xa[r * K1_SSTR + c] = __float2half_rn(x[(size_t)(m0 + r) * NUM_IN + c]);
        wb[r * K1_SSTR + c] = __float2half_rn(W1[(size_t)(n0 + r) * NUM_IN + c]);
    }
    if (tid < 128) bs[tid] = b1[n0 + tid];
    __syncthreads();

    float acc[2][8][4];
#pragma unroll
    for (int mt = 0; mt < 2; mt++)
#pragma unroll
        for (int nt = 0; nt < 8; nt++)
#pragma unroll
            for (int j = 0; j < 4; j++) acc[mt][nt][j] = 0.0f;

#pragma unroll
    for (int ks = 0; ks < 2; ks++) {
        const int kc = ks * 16 + 2 * t;
        uint32_t af[2][4];
#pragma unroll
        for (int mt = 0; mt < 2; mt++) {
            const __half* ap = xa + (wm + mt * 16 + g) * K1_SSTR + kc;
            af[mt][0] = *(const uint32_t*)(ap);
            af[mt][1] = *(const uint32_t*)(ap + 8 * K1_SSTR);
            af[mt][2] = *(const uint32_t*)(ap + 8);
            af[mt][3] = *(const uint32_t*)(ap + 8 * K1_SSTR + 8);
        }
#pragma unroll
        for (int nt = 0; nt < 8; nt++) {
            const __half* bp = wb + (wn + nt * 8 + g) * K1_SSTR + kc;
            uint32_t bf[2];
            bf[0] = *(const uint32_t*)(bp);
            bf[1] = *(const uint32_t*)(bp + 8);
            mma16(acc[0][nt], af[0], bf);
            mma16(acc[1][nt], af[1], bf);
        }
    }

#pragma unroll
    for (int nt = 0; nt < 8; nt++) {
        const int col = wn + nt * 8 + t * 2;
        const float b0 = bs[col], b1v = bs[col + 1];
#pragma unroll
        for (int q = 0; q < 4; q++) {
            const int mt = q >> 1, h = q & 1;
            const int row = m0 + wm + mt * 16 + h * 8 + g;
            const float v0 = fmaxf(acc[mt][nt][h * 2 + 0] + b0, 0.0f);
            const float v1 = fmaxf(acc[mt][nt][h * 2 + 1] + b1v, 0.0f);
            *(__half2*)&g_h[(size_t)row * H1 + n0 + col] = __floats2half2_rn(v0, v1);
        }
    }
}

// ---------------------------------------------------------------------------
// Kernel 2: persistent fp16 mma GEMM (R11 verbatim). BM=128, BN=128, BK=32,
// 4-stage cp.async. grid 296, block 256.
// ---------------------------------------------------------------------------
#define SSTRH    40
#define TILE_H   (128 * SSTRH)
#define STAGE_H  (2 * TILE_H)
#define STAGE_B  (STAGE_H * 2)
#define TILE_B   (TILE_H * 2)
#define K2_SMEM_BYTES (4 * STAGE_B)
#define NTILES   2048
#define K2_GRID  296

__global__ __launch_bounds__(256, 2) void k2_mma(
    const float* __restrict__ b21,  const float* __restrict__ bobs1,
    const float* __restrict__ W31,  const float* __restrict__ Wobs2)
{
    extern __shared__ __half smh[];
    __shared__ float ws[2][128];
    __shared__ float sred[2][128][2];

    const int tid  = threadIdx.x;
    const int wid  = tid >> 5;
    const int lane = tid & 31;
    const int g    = lane >> 2;
    const int t    = lane & 3;
    const int wm   = (wid & 3) * 32;
    const int wn   = (wid >> 2) * 64;
    const int half = wid >> 2;

    uint32_t smem_base;
    asm("{ .reg .u64 t; cvta.to.shared.u64 t, %1; cvt.u32.u64 %0, t; }"
        : "=r"(smem_base) : "l"(smh));

    const int lm = tid >> 2;
    const int lq = tid & 3;
    const uint32_t dOff = (uint32_t)(lm * SSTRH * 2 + lq * 16);

    const int lr  = lane & 7;
    const int sel = lane >> 3;
    uint32_t aOffL[2];
#pragma unroll
    for (int mt = 0; mt < 2; mt++)
        aOffL[mt] = (uint32_t)(((wm + mt * 16 + lr + (sel & 1) * 8) * SSTRH
                               + (sel >> 1) * 8) * 2);
    uint32_t bOffL[4];
#pragma unroll
    for (int np = 0; np < 4; np++)
        bOffL[np] = (uint32_t)(TILE_B + ((wn + np * 16 + lr + (sel >> 1) * 8) * SSTRH
                               + (sel & 1) * 8) * 2);

    for (int tile = blockIdx.x; tile < NTILES; tile += K2_GRID) {
        const int m0 = (tile >> 3) * 128;
        const int n0 = (tile & 7) * 128;
        const int pair = (n0 >= 512);

        const float* bsrc = pair ? (bobs1 + (n0 - 512)) : (b21 + n0);
        const float* w0g  = pair ? (Wobs2 + (n0 - 512)) : (W31 + n0);
        const float* w1g  = pair ? (Wobs2 + 512 + (n0 - 512)) : (W31 + 512 + n0);

        const __half* aG = &g_h [(size_t)(m0 + lm) * H1 + lq * 8];
        const __half* bG = &g_wh[(size_t)(n0 + lm) * H1 + lq * 8];

        float acc[2][8][4];
#pragma unroll
        for (int mt = 0; mt < 2; mt++)
#pragma unroll
            for (int nt = 0; nt < 8; nt++)
#pragma unroll
                for (int j = 0; j < 4; j++) acc[mt][nt][j] = 0.0f;

        // ---- prologue: stages 0..2 ----
#pragma unroll
        for (int p = 0; p < 3; p++) {
            const uint32_t aB = smem_base + p * STAGE_B + dOff;
            const uint32_t bB = aB + (uint32_t)TILE_B;
            const int k0 = p * 32;
#pragma unroll
            for (int i = 0; i < 2; i++) {
                cpa_cg(aB + i * 64 * SSTRH * 2, aG + (size_t)i * 64 * H1 + k0);
                cpa_ca(bB + i * 64 * SSTRH * 2, bG + (size_t)i * 64 * H1 + k0);
            }
            asm volatile("cp.async.commit_group;");
        }

        // ---- 32 slabs of BK=32 ----
        for (int s = 0; s < 32; s++) {
            const int stg = s & 3;
            asm volatile("cp.async.wait_group 2;");
            __syncthreads();

            if (s + 3 < 32) {
                const int pst = (s + 3) & 3;
                const uint32_t aB = smem_base + pst * STAGE_B + dOff;
                const uint32_t bB = aB + (uint32_t)TILE_B;
                const int k0 = (s + 3) * 32;
#pragma unroll
                for (int i = 0; i < 2; i++) {
                    cpa_cg(aB + i * 64 * SSTRH * 2, aG + (size_t)i * 64 * H1 + k0);
                    cpa_ca(bB + i * 64 * SSTRH * 2, bG + (size_t)i * 64 * H1 + k0);
                }
            }
            asm volatile("cp.async.commit_group;");

            {
                const uint32_t tb = smem_base + stg * STAGE_B;
#pragma unroll
                for (int ks = 0; ks < 2; ks++) {
                    const uint32_t kb = tb + ks * 32;
                    uint32_t af[2][4];
                    ldmx4(af[0], kb + aOffL[0]);
                    ldmx4(af[1], kb + aOffL[1]);
#pragma unroll
                    for (int np = 0; np < 4; np++) {
                        uint32_t bf[4];
                        ldmx4(bf, kb + bOffL[np]);
                        mma16(acc[0][2 * np + 0], af[0], bf);
                        mma16(acc[0][2 * np + 1], af[0], bf + 2);
                        mma16(acc[1][2 * np + 0], af[1], bf);
                        mma16(acc[1][2 * np + 1], af[1], bf + 2);
                    }
                }
            }
        }

        // ---- epilogue: relu + partial layer-3 dots ----
        if (tid < 128) ws[0][tid] = w0g[tid];
        else           ws[1][tid - 128] = w1g[tid - 128];
        __syncthreads();

        float u[4][2];
#pragma unroll
        for (int q = 0; q < 4; q++) { u[q][0] = 0.0f; u[q][1] = 0.0f; }

#pragma unroll
        for (int nt = 0; nt < 8; nt++) {
            const int col = wn + nt * 8 + t * 2;
            const float2 bb = *(const float2*)&bsrc[col];
            const float wa0 = ws[0][col], wa1 = ws[0][col + 1];
            const float wb0 = ws[1][col], wb1 = ws[1][col + 1];
#pragma unroll
            for (int q = 0; q < 4; q++) {
                const int mt = q >> 1, h = q & 1;
                const float v0 = fmaxf(acc[mt][nt][h * 2 + 0] + bb.x, 0.0f);
                const float v1 = fmaxf(acc[mt][nt][h * 2 + 1] + bb.y, 0.0f);
                u[q][0] = fmaf(v0, wa0, fmaf(v1, wa1, u[q][0]));
                u[q][1] = fmaf(v0, wb0, fmaf(v1, wb1, u[q][1]));
            }
        }

#pragma unroll
        for (int q = 0; q < 4; q++)
#pragma unroll
            for (int c = 0; c < 2; c++) {
                u[q][c] += __shfl_xor_sync(0xFFFFFFFFu, u[q][c], 1);
                u[q][c] += __shfl_xor_sync(0xFFFFFFFFu, u[q][c], 2);
            }

        if (t == 0) {
#pragma unroll
            for (int q = 0; q < 4; q++) {
                const int row = wm + (q >> 1) * 16 + (q & 1) * 8 + g;
                sred[half][row][0] = u[q][0];
                sred[half][row][1] = u[q][1];
            }
        }
        __syncthreads();

        {
            const int row = tid >> 1;
            const int c   = tid & 1;
            const float sum = sred[0][row][c] + sred[1][row][c];
            const int nb4 = tile & 3;
            g_part[(size_t)(m0 + row) * 16 + pair * 8 + nb4 * 2 + c] = sum;
        }
        __syncthreads();
    }
}

// ---------------------------------------------------------------------------
// Kernel 3: per-row partial sum + sigmoid + CBF epilogue. grid 128, block 256.
// ---------------------------------------------------------------------------
__global__ __launch_bounds__(256) void k3_final(
    const float* __restrict__ x,
    const float* __restrict__ mean_, const float* __restrict__ stdv,
    const float* __restrict__ b31,   const float* __restrict__ bobs2,
    float* __restrict__ out)
{
    const int row = blockIdx.x * 256 + threadIdx.x;

    const float* pp = &g_part[(size_t)row * 16];
    float4 pa = *(const float4*)&pp[0];
    float4 pb = *(const float4*)&pp[4];
    float4 pc = *(const float4*)&pp[8];
    float4 pd = *(const float4*)&pp[12];

    const float x31_0 = pa.x + pa.z + pb.x + pb.z + b31[0];
    const float x31_1 = pa.y + pa.w + pb.y + pb.w + b31[1];
    const float t0    = pc.x + pc.z + pd.x + pd.z + bobs2[0];
    const float t1    = pc.y + pc.w + pd.y + pd.w + bobs2[1];
    const float p0 = 4.0f / (1.0f + expf(-t0));
    const float p1 = 4.0f / (1.0f + expf(-t1));

    const float* xr = x + (size_t)row * NUM_IN;
    float x0v[NUM_IN];
#pragma unroll
    for (int c = 2; c < NUM_IN; c++) x0v[c] = fmaf(xr[c], stdv[c], mean_[c]);

    const float theta = x0v[2];
    const float v     = x0v[3];
    const float st = sinf(theta), ct = cosf(theta);
    const float ox = x0v[4], oy = x0v[5], oth = x0v[6], ov = x0v[7];
    const float dx = -ox, dy = -oy;
    const float ost = sinf(oth), oct = cosf(oth);
    const float R2 = 0.45f * 0.45f;

    const float barrier = dx * dx + dy * dy - R2;
    const float bdot    = 2.0f * dx * (v * ct - ov * oct)
                        + 2.0f * dy * (v * st - ov * ost);
    const float Lf2b    = 2.0f * (v * v + ov * ov
                        - 2.0f * v * ov * cosf(theta + oth));
    const float Gu1 = -2.0f * dx * v * st + 2.0f * dy * v * ct;
    const float Gu2 =  2.0f * dx * ct + 2.0f * dy * st;

    const float psum  = p0 + p1;
    const float pprod = p0 * p1;

    float o[14];
    o[0]  = x31_0;
    o[1]  = x31_1;
    o[2]  = -Gu1;
    o[3]  = -Gu2;
    o[10] = Lf2b + psum * bdot + pprod * barrier;

    const float sLf2b = 2.0f * v * v;
#pragma unroll
    for (int j = 0; j < 3; j++) {
        const float sdx = -x0v[8 + 4 * j];
        const float sdy = -x0v[9 + 4 * j];
        const float sb    = sdx * sdx + sdy * sdy - R2;
        const float sbdot = 2.0f * sdx * v * ct + 2.0f * sdy * v * st;
        const float sGu1  = -2.0f * sdx * v * st + 2.0f * sdy * v * ct;
        const float sGu2  =  2.0f * sdx * ct + 2.0f * sdy * st;
        o[4 + 2 * j] = -sGu1;
        o[5 + 2 * j] = -sGu2;
        o[11 + j]    = sLf2b + psum * sbdot + pprod * sb;
    }

    float* op = out + (size_t)row * 14;
#pragma unroll
    for (int i = 0; i < 14; i++) op[i] = o[i];
}

// ---------------------------------------------------------------------------
// Launch
// ---------------------------------------------------------------------------
extern "C" void kernel_launch(void* const* d_in, const int* in_sizes, int n_in,
                              void* d_out, int out_size)
{
    const float* x      = (const float*)d_in[0];
    const float* mean_  = (const float*)d_in[2];
    const float* stdv   = (const float*)d_in[3];
    const float* W1     = (const float*)d_in[4];
    const float* b1     = (const float*)d_in[5];
    const float* W21    = (const float*)d_in[6];
    const float* b21    = (const float*)d_in[7];
    const float* W31    = (const float*)d_in[8];
    const float* b31    = (const float*)d_in[9];
    const float* Wobs1  = (const float*)d_in[10];
    const float* bobs1  = (const float*)d_in[11];
    const float* Wobs2  = (const float*)d_in[12];
    const float* bobs2  = (const float*)d_in[13];
    float* out = (float*)d_out;

    cudaFuncSetAttribute(k2_mma, cudaFuncAttributeMaxDynamicSharedMemorySize,
                         K2_SMEM_BYTES);

    k01_l1_and_convert<<<3072, 256>>>(x, W1, b1, W21, Wobs1);
    k2_mma<<<K2_GRID, 256, K2_SMEM_BYTES>>>(b21, bobs1, W31, Wobs2);
    k3_final<<<B_ROWS / 256, 256>>>(x, mean_, stdv, b31, bobs2, out);
}

// round 14
// speedup vs baseline: 1.0245x; 1.0019x over previous
#include <cuda_runtime.h>
#include <cuda_fp16.h>
#include <math.h>
#include <stdint.h>

// ---------------------------------------------------------------------------
// LiveNet fused forward (sm_100 plain target; fp16 mma.sync + ldmatrix).
//   K01: blocks 0..2047  -> layer-1 mma tiles (single-pass masked fp32->fp16)
//        blocks 2048..3071 -> [W21;Wobs1] fp32->fp16 conversion (overlapped)
//   K2 : persistent fp16 GEMM h @ g_wh^T (BK=32, 4-stage), fused relu +
//        layer-3 partial dots -> g_part
//   K3 : sum partials, sigmoid, CBF epilogue -> out [32768,14]
// ---------------------------------------------------------------------------

#define B_ROWS 32768
#define NUM_IN 20
#define H1     1024

__device__ __half g_h  [(size_t)B_ROWS * H1];
__device__ __half g_wh [(size_t)1024 * H1];
__device__ float  g_part[(size_t)B_ROWS * 16];

// ---------------------------------------------------------------------------
// helpers
// ---------------------------------------------------------------------------
__device__ __forceinline__ void mma16(float* c, const uint32_t* a, const uint32_t* b) {
    asm volatile(
        "mma.sync.aligned.m16n8k16.row.col.f32.f16.f16.f32 "
        "{%0,%1,%2,%3}, {%4,%5,%6,%7}, {%8,%9}, {%0,%1,%2,%3};"
        : "+f"(c[0]), "+f"(c[1]), "+f"(c[2]), "+f"(c[3])
        : "r"(a[0]), "r"(a[1]), "r"(a[2]), "r"(a[3]), "r"(b[0]), "r"(b[1]));
}

__device__ __forceinline__ void ldmx4(uint32_t* r, uint32_t addr) {
    asm volatile("ldmatrix.sync.aligned.m8n8.x4.shared.b16 {%0,%1,%2,%3}, [%4];"
                 : "=r"(r[0]), "=r"(r[1]), "=r"(r[2]), "=r"(r[3]) : "r"(addr));
}

__device__ __forceinline__ void cpa_cg(uint32_t d, const __half* s) {
    asm volatile("cp.async.cg.shared.global [%0], [%1], 16;" :: "r"(d), "l"(s));
}
__device__ __forceinline__ void cpa_ca(uint32_t d, const __half* s) {
    asm volatile("cp.async.ca.shared.global [%0], [%1], 16;" :: "r"(d), "l"(s));
}

// ---------------------------------------------------------------------------
// Kernel 01: layer-1 mma tiles + overlapped weight conversion.
// grid 3072 (1D), block 256.
// ---------------------------------------------------------------------------
#define K1_SSTR 40

__global__ __launch_bounds__(256) void k01_l1_and_convert(
    const float* __restrict__ x,   const float* __restrict__ W1,
    const float* __restrict__ b1,
    const float* __restrict__ W21, const float* __restrict__ Wobs1)
{
    const int tid = threadIdx.x;

    if (blockIdx.x >= 2048) {
        // ---- weight conversion: [W21;Wobs1] -> g_wh (fp16) ----
        const size_t i4 = ((size_t)(blockIdx.x - 2048) * 256 + tid) * 4;
        const size_t half_total = (size_t)512 * H1;
        const float* src = (i4 < half_total) ? (W21 + i4) : (Wobs1 + (i4 - half_total));
        float4 v = *(const float4*)src;
        __half2* dst = (__half2*)&g_wh[i4];
        dst[0] = __floats2half2_rn(v.x, v.y);
        dst[1] = __floats2half2_rn(v.z, v.w);
        return;
    }

    // ---- layer-1 mma tile ----
    __shared__ __half xa[128 * K1_SSTR];
    __shared__ __half wb[128 * K1_SSTR];
    __shared__ float  bs[128];

    const int wid  = tid >> 5;
    const int lane = tid & 31;
    const int g    = lane >> 2;
    const int t    = lane & 3;
    const int wm   = (wid & 3) * 32;
    const int wn   = (wid >> 2) * 64;

    const int m0 = (blockIdx.x >> 3) * 128;
    const int n0 = (blockIdx.x & 7) * 128;

    // single-pass masked fill: K padded to 32, power-of-2 indexing, no IDIV
#pragma unroll
    for (int it = 0; it < 16; it++) {
        const int i = tid + it * 256;
        const int r = i >> 5, c = i & 31;
        const bool real = (c < NUM_IN);
        const float xv = real ? x [(size_t)(m0 + r) * NUM_IN + c] : 0.0f;
        const float wv = real ? W1[(size_t)(n0 + r) * NUM_IN + c] : 0.0f;
        xa[r * K1_SSTR + c] = __float2half_rn(xv);
        wb[r * K1_SSTR + c] = __float2half_rn(wv);
    }
    if (tid < 128) bs[tid] = b1[n0 + tid];
    __syncthreads();

    float acc[2][8][4];
#pragma unroll
    for (int mt = 0; mt < 2; mt++)
#pragma unroll
        for (int nt = 0; nt < 8; nt++)
#pragma unroll
            for (int j = 0; j < 4; j++) acc[mt][nt][j] = 0.0f;

#pragma unroll
    for (int ks = 0; ks < 2; ks++) {
        const int kc = ks * 16 + 2 * t;
        uint32_t af[2][4];
#pragma unroll
        for (int mt = 0; mt < 2; mt++) {
            const __half* ap = xa + (wm + mt * 16 + g) * K1_SSTR + kc;
            af[mt][0] = *(const uint32_t*)(ap);
            af[mt][1] = *(const uint32_t*)(ap + 8 * K1_SSTR);
            af[mt][2] = *(const uint32_t*)(ap + 8);
            af[mt][3] = *(const uint32_t*)(ap + 8 * K1_SSTR + 8);
        }
#pragma unroll
        for (int nt = 0; nt < 8; nt++) {
            const __half* bp = wb + (wn + nt * 8 + g) * K1_SSTR + kc;
            uint32_t bf[2];
            bf[0] = *(const uint32_t*)(bp);
            bf[1] = *(const uint32_t*)(bp + 8);
            mma16(acc[0][nt], af[0], bf);
            mma16(acc[1][nt], af[1], bf);
        }
    }

#pragma unroll
    for (int nt = 0; nt < 8; nt++) {
        const int col = wn + nt * 8 + t * 2;
        const float b0 = bs[col], b1v = bs[col + 1];
#pragma unroll
        for (int q = 0; q < 4; q++) {
            const int mt = q >> 1, h = q & 1;
            const int row = m0 + wm + mt * 16 + h * 8 + g;
            const float v0 = fmaxf(acc[mt][nt][h * 2 + 0] + b0, 0.0f);
            const float v1 = fmaxf(acc[mt][nt][h * 2 + 1] + b1v, 0.0f);
            *(__half2*)&g_h[(size_t)row * H1 + n0 + col] = __floats2half2_rn(v0, v1);
        }
    }
}

// ---------------------------------------------------------------------------
// Kernel 2: persistent fp16 mma GEMM. BM=128, BN=128, BK=32, 4-stage
// cp.async. grid 296, block 256.
// ---------------------------------------------------------------------------
#define SSTRH    40
#define TILE_H   (128 * SSTRH)
#define STAGE_H  (2 * TILE_H)
#define STAGE_B  (STAGE_H * 2)
#define TILE_B   (TILE_H * 2)
#define K2_SMEM_BYTES (4 * STAGE_B)
#define NTILES   2048
#define K2_GRID  296

__global__ __launch_bounds__(256, 2) void k2_mma(
    const float* __restrict__ b21,  const float* __restrict__ bobs1,
    const float* __restrict__ W31,  const float* __restrict__ Wobs2)
{
    extern __shared__ __half smh[];
    __shared__ float ws[2][128];
    __shared__ float sred[2][128][2];

    const int tid  = threadIdx.x;
    const int wid  = tid >> 5;
    const int lane = tid & 31;
    const int g    = lane >> 2;
    const int t    = lane & 3;
    const int wm   = (wid & 3) * 32;
    const int wn   = (wid >> 2) * 64;
    const int half = wid >> 2;

    uint32_t smem_base;
    asm("{ .reg .u64 t; cvta.to.shared.u64 t, %1; cvt.u32.u64 %0, t; }"
        : "=r"(smem_base) : "l"(smh));

    const int lm = tid >> 2;
    const int lq = tid & 3;
    const uint32_t dOff = (uint32_t)(lm * SSTRH * 2 + lq * 16);

    const int lr  = lane & 7;
    const int sel = lane >> 3;
    uint32_t aOffL[2];
#pragma unroll
    for (int mt = 0; mt < 2; mt++)
        aOffL[mt] = (uint32_t)(((wm + mt * 16 + lr + (sel & 1) * 8) * SSTRH
                               + (sel >> 1) * 8) * 2);
    uint32_t bOffL[4];
#pragma unroll
    for (int np = 0; np < 4; np++)
        bOffL[np] = (uint32_t)(TILE_B + ((wn + np * 16 + lr + (sel >> 1) * 8) * SSTRH
                               + (sel & 1) * 8) * 2);

    for (int tile = blockIdx.x; tile < NTILES; tile += K2_GRID) {
        const int m0 = (tile >> 3) * 128;
        const int n0 = (tile & 7) * 128;
        const int pair = (n0 >= 512);

        const float* bsrc = pair ? (bobs1 + (n0 - 512)) : (b21 + n0);
        const float* w0g  = pair ? (Wobs2 + (n0 - 512)) : (W31 + n0);
        const float* w1g  = pair ? (Wobs2 + 512 + (n0 - 512)) : (W31 + 512 + n0);

        const __half* aG = &g_h [(size_t)(m0 + lm) * H1 + lq * 8];
        const __half* bG = &g_wh[(size_t)(n0 + lm) * H1 + lq * 8];

        float acc[2][8][4];
#pragma unroll
        for (int mt = 0; mt < 2; mt++)
#pragma unroll
            for (int nt = 0; nt < 8; nt++)
#pragma unroll
                for (int j = 0; j < 4; j++) acc[mt][nt][j] = 0.0f;

        // ---- prologue: stages 0..2 ----
#pragma unroll
        for (int p = 0; p < 3; p++) {
            const uint32_t aB = smem_base + p * STAGE_B + dOff;
            const uint32_t bB = aB + (uint32_t)TILE_B;
            const int k0 = p * 32;
#pragma unroll
            for (int i = 0; i < 2; i++) {
                cpa_cg(aB + i * 64 * SSTRH * 2, aG + (size_t)i * 64 * H1 + k0);
                cpa_ca(bB + i * 64 * SSTRH * 2, bG + (size_t)i * 64 * H1 + k0);
            }
            asm volatile("cp.async.commit_group;");
        }

        // ---- 32 slabs of BK=32 ----
        for (int s = 0; s < 32; s++) {
            const int stg = s & 3;
            asm volatile("cp.async.wait_group 2;");
            __syncthreads();

            if (s + 3 < 32) {
                const int pst = (s + 3) & 3;
                const uint32_t aB = smem_base + pst * STAGE_B + dOff;
                const uint32_t bB = aB + (uint32_t)TILE_B;
                const int k0 = (s + 3) * 32;
#pragma unroll
                for (int i = 0; i < 2; i++) {
                    cpa_cg(aB + i * 64 * SSTRH * 2, aG + (size_t)i * 64 * H1 + k0);
                    cpa_ca(bB + i * 64 * SSTRH * 2, bG + (size_t)i * 64 * H1 + k0);
                }
            }
            asm volatile("cp.async.commit_group;");

            {
                const uint32_t tb = smem_base + stg * STAGE_B;
#pragma unroll
                for (int ks = 0; ks < 2; ks++) {
                    const uint32_t kb = tb + ks * 32;
                    uint32_t af[2][4];
                    ldmx4(af[0], kb + aOffL[0]);
                    ldmx4(af[1], kb + aOffL[1]);
#pragma unroll
                    for (int np = 0; np < 4; np++) {
                        uint32_t bf[4];
                        ldmx4(bf, kb + bOffL[np]);
                        mma16(acc[0][2 * np + 0], af[0], bf);
                        mma16(acc[0][2 * np + 1], af[0], bf + 2);
                        mma16(acc[1][2 * np + 0], af[1], bf);
                        mma16(acc[1][2 * np + 1], af[1], bf + 2);
                    }
                }
            }
        }

        // ---- epilogue: relu + partial layer-3 dots ----
        if (tid < 128) ws[0][tid] = w0g[tid];
        else           ws[1][tid - 128] = w1g[tid - 128];
        __syncthreads();

        float u[4][2];
#pragma unroll
        for (int q = 0; q < 4; q++) { u[q][0] = 0.0f; u[q][1] = 0.0f; }

#pragma unroll
        for (int nt = 0; nt < 8; nt++) {
            const int col = wn + nt * 8 + t * 2;
            const float2 bb = *(const float2*)&bsrc[col];
            const float wa0 = ws[0][col], wa1 = ws[0][col + 1];
            const float wb0 = ws[1][col], wb1 = ws[1][col + 1];
#pragma unroll
            for (int q = 0; q < 4; q++) {
                const int mt = q >> 1, h = q & 1;
                const float v0 = fmaxf(acc[mt][nt][h * 2 + 0] + bb.x, 0.0f);
                const float v1 = fmaxf(acc[mt][nt][h * 2 + 1] + bb.y, 0.0f);
                u[q][0] = fmaf(v0, wa0, fmaf(v1, wa1, u[q][0]));
                u[q][1] = fmaf(v0, wb0, fmaf(v1, wb1, u[q][1]));
            }
        }

#pragma unroll
        for (int q = 0; q < 4; q++)
#pragma unroll
            for (int c = 0; c < 2; c++) {
                u[q][c] += __shfl_xor_sync(0xFFFFFFFFu, u[q][c], 1);
                u[q][c] += __shfl_xor_sync(0xFFFFFFFFu, u[q][c], 2);
            }

        if (t == 0) {
#pragma unroll
            for (int q = 0; q < 4; q++) {
                const int row = wm + (q >> 1) * 16 + (q & 1) * 8 + g;
                sred[half][row][0] = u[q][0];
                sred[half][row][1] = u[q][1];
            }
        }
        __syncthreads();

        {
            const int row = tid >> 1;
            const int c   = tid & 1;
            const float sum = sred[0][row][c] + sred[1][row][c];
            const int nb4 = tile & 3;
            g_part[(size_t)(m0 + row) * 16 + pair * 8 + nb4 * 2 + c] = sum;
        }
        __syncthreads();
    }
}

// ---------------------------------------------------------------------------
// Kernel 3: per-row partial sum + sigmoid + CBF epilogue. grid 128, block 256.
// ---------------------------------------------------------------------------
__global__ __launch_bounds__(256) void k3_final(
    const float* __restrict__ x,
    const float* __restrict__ mean_, const float* __restrict__ stdv,
    const float* __restrict__ b31,   const float* __restrict__ bobs2,
    float* __restrict__ out)
{
    const int row = blockIdx.x * 256 + threadIdx.x;

    const float* pp = &g_part[(size_t)row * 16];
    float4 pa = *(const float4*)&pp[0];
    float4 pb = *(const float4*)&pp[4];
    float4 pc = *(const float4*)&pp[8];
    float4 pd = *(const float4*)&pp[12];

    const float x31_0 = pa.x + pa.z + pb.x + pb.z + b31[0];
    const float x31_1 = pa.y + pa.w + pb.y + pb.w + b31[1];
    const float t0    = pc.x + pc.z + pd.x + pd.z + bobs2[0];
    const float t1    = pc.y + pc.w + pd.y + pd.w + bobs2[1];
    const float p0 = 4.0f / (1.0f + expf(-t0));
    const float p1 = 4.0f / (1.0f + expf(-t1));

    const float* xr = x + (size_t)row * NUM_IN;
    float x0v[NUM_IN];
#pragma unroll
    for (int c = 2; c < NUM_IN; c++) x0v[c] = fmaf(xr[c], stdv[c], mean_[c]);

    const float theta = x0v[2];
    const float v     = x0v[3];
    const float st = sinf(theta), ct = cosf(theta);
    const float ox = x0v[4], oy = x0v[5], oth = x0v[6], ov = x0v[7];
    const float dx = -ox, dy = -oy;
    const float ost = sinf(oth), oct = cosf(oth);
    const float R2 = 0.45f * 0.45f;

    const float barrier = dx * dx + dy * dy - R2;
    const float bdot    = 2.0f * dx * (v * ct - ov * oct)
                        + 2.0f * dy * (v * st - ov * ost);
    const float Lf2b    = 2.0f * (v * v + ov * ov
                        - 2.0f * v * ov * cosf(theta + oth));
    const float Gu1 = -2.0f * dx * v * st + 2.0f * dy * v * ct;
    const float Gu2 =  2.0f * dx * ct + 2.0f * dy * st;

    const float psum  = p0 + p1;
    const float pprod = p0 * p1;

    float o[14];
    o[0]  = x31_0;
    o[1]  = x31_1;
    o[2]  = -Gu1;
    o[3]  = -Gu2;
    o[10] = Lf2b + psum * bdot + pprod * barrier;

    const float sLf2b = 2.0f * v * v;
#pragma unroll
    for (int j = 0; j < 3; j++) {
        const float sdx = -x0v[8 + 4 * j];
        const float sdy = -x0v[9 + 4 * j];
        const float sb    = sdx * sdx + sdy * sdy - R2;
        const float sbdot = 2.0f * sdx * v * ct + 2.0f * sdy * v * st;
        const float sGu1  = -2.0f * sdx * v * st + 2.0f * sdy * v * ct;
        const float sGu2  =  2.0f * sdx * ct + 2.0f * sdy * st;
        o[4 + 2 * j] = -sGu1;
        o[5 + 2 * j] = -sGu2;
        o[11 + j]    = sLf2b + psum * sbdot + pprod * sb;
    }

    float* op = out + (size_t)row * 14;
#pragma unroll
    for (int i = 0; i < 14; i++) op[i] = o[i];
}

// ---------------------------------------------------------------------------
// Launch
// ---------------------------------------------------------------------------
extern "C" void kernel_launch(void* const* d_in, const int* in_sizes, int n_in,
                              void* d_out, int out_size)
{
    const float* x      = (const float*)d_in[0];
    const float* mean_  = (const float*)d_in[2];
    const float* stdv   = (const float*)d_in[3];
    const float* W1     = (const float*)d_in[4];
    const float* b1     = (const float*)d_in[5];
    const float* W21    = (const float*)d_in[6];
    const float* b21    = (const float*)d_in[7];
    const float* W31    = (const float*)d_in[8];
    const float* b31    = (const float*)d_in[9];
    const float* Wobs1  = (const float*)d_in[10];
    const float* bobs1  = (const float*)d_in[11];
    const float* Wobs2  = (const float*)d_in[12];
    const float* bobs2  = (const float*)d_in[13];
    float* out = (float*)d_out;

    cudaFuncSetAttribute(k2_mma, cudaFuncAttributeMaxDynamicSharedMemorySize,
                         K2_SMEM_BYTES);

    k01_l1_and_convert<<<3072, 256>>>(x, W1, b1, W21, Wobs1);
    k2_mma<<<K2_GRID, 256, K2_SMEM_BYTES>>>(b21, bobs1, W31, Wobs2);
    k3_final<<<B_ROWS / 256, 256>>>(x, mean_, stdv, b31, bobs2, out);
}

// round 15
// speedup vs baseline: 1.0542x; 1.0289x over previous
#include <cuda_runtime.h>
#include <cuda_fp16.h>
#include <math.h>
#include <stdint.h>

// ---------------------------------------------------------------------------
// LiveNet fused forward (sm_100 plain target; fp16 mma.sync + ldmatrix).
//   K01: blocks 0..2047  -> layer-1 mma tiles (vector fill, staged stores)
//        blocks 2048..3071 -> [W21;Wobs1] fp32->fp16 conversion (overlapped)
//   K2 : persistent fp16 GEMM h @ g_wh^T (BK=32, 4-stage), fused relu +
//        layer-3 partial dots -> g_part
//   K3 : sum partials, sigmoid, CBF epilogue -> out [32768,14]
// ---------------------------------------------------------------------------

#define B_ROWS 32768
#define NUM_IN 20
#define H1     1024

__device__ __half g_h  [(size_t)B_ROWS * H1];
__device__ __half g_wh [(size_t)1024 * H1];
__device__ float  g_part[(size_t)B_ROWS * 16];

// ---------------------------------------------------------------------------
// helpers
// ---------------------------------------------------------------------------
__device__ __forceinline__ void mma16(float* c, const uint32_t* a, const uint32_t* b) {
    asm volatile(
        "mma.sync.aligned.m16n8k16.row.col.f32.f16.f16.f32 "
        "{%0,%1,%2,%3}, {%4,%5,%6,%7}, {%8,%9}, {%0,%1,%2,%3};"
        : "+f"(c[0]), "+f"(c[1]), "+f"(c[2]), "+f"(c[3])
        : "r"(a[0]), "r"(a[1]), "r"(a[2]), "r"(a[3]), "r"(b[0]), "r"(b[1]));
}

__device__ __forceinline__ void ldmx4(uint32_t* r, uint32_t addr) {
    asm volatile("ldmatrix.sync.aligned.m8n8.x4.shared.b16 {%0,%1,%2,%3}, [%4];"
                 : "=r"(r[0]), "=r"(r[1]), "=r"(r[2]), "=r"(r[3]) : "r"(addr));
}

__device__ __forceinline__ void cpa_cg(uint32_t d, const __half* s) {
    asm volatile("cp.async.cg.shared.global [%0], [%1], 16;" :: "r"(d), "l"(s));
}
__device__ __forceinline__ void cpa_ca(uint32_t d, const __half* s) {
    asm volatile("cp.async.ca.shared.global [%0], [%1], 16;" :: "r"(d), "l"(s));
}

// ---------------------------------------------------------------------------
// Kernel 01: layer-1 mma tiles + overlapped weight conversion.
// grid 3072 (1D), block 256.
// ---------------------------------------------------------------------------
#define K1_SSTR 40          // fill-phase smem row stride (halfs)
#define ST_STR  136         // staging row stride (halfs): banks 4g+t distinct

__global__ __launch_bounds__(256) void k01_l1_and_convert(
    const float* __restrict__ x,   const float* __restrict__ W1,
    const float* __restrict__ b1,
    const float* __restrict__ W21, const float* __restrict__ Wobs1)
{
    const int tid = threadIdx.x;

    if (blockIdx.x >= 2048) {
        // ---- weight conversion: [W21;Wobs1] -> g_wh (fp16) ----
        const size_t i4 = ((size_t)(blockIdx.x - 2048) * 256 + tid) * 4;
        const size_t half_total = (size_t)512 * H1;
        const float* src = (i4 < half_total) ? (W21 + i4) : (Wobs1 + (i4 - half_total));
        float4 v = *(const float4*)src;
        __half2* dst = (__half2*)&g_wh[i4];
        dst[0] = __floats2half2_rn(v.x, v.y);
        dst[1] = __floats2half2_rn(v.z, v.w);
        return;
    }

    // ---- layer-1 mma tile ----
    // pool: xa = pool[0 .. 5120), wb = pool[5120 .. 10240); staging reuses pool.
    __shared__ __half pool[128 * K1_SSTR * 2];
    __shared__ float  bs[128];
    __half* xa = pool;
    __half* wb = pool + 128 * K1_SSTR;

    const int wid  = tid >> 5;
    const int lane = tid & 31;
    const int g    = lane >> 2;
    const int t    = lane & 3;
    const int wmi  = wid & 3;          // warp m index (0..3)
    const int wm   = wmi * 32;
    const int wn   = (wid >> 2) * 64;

    const int m0 = (blockIdx.x >> 3) * 128;
    const int n0 = (blockIdx.x & 7) * 128;

    // ---- vector fill: 5 float4 per 20-float row ----
    for (int i = tid; i < 640; i += 256) {
        const int r = i / 5, q = i - r * 5;
        float4 xv = *(const float4*)&x [(size_t)(m0 + r) * NUM_IN + q * 4];
        float4 wv = *(const float4*)&W1[(size_t)(n0 + r) * NUM_IN + q * 4];
        __half2* xd = (__half2*)&xa[r * K1_SSTR + q * 4];
        __half2* wd = (__half2*)&wb[r * K1_SSTR + q * 4];
        xd[0] = __floats2half2_rn(xv.x, xv.y);
        xd[1] = __floats2half2_rn(xv.z, xv.w);
        wd[0] = __floats2half2_rn(wv.x, wv.y);
        wd[1] = __floats2half2_rn(wv.z, wv.w);
    }
    // zero pad cols 20..31 (3 x 8B per row)
    {
        const __half2 z2 = __floats2half2_rn(0.0f, 0.0f);
        for (int i = tid; i < 384; i += 256) {
            const int r = i / 3, j = i - r * 3;
            __half2* xd = (__half2*)&xa[r * K1_SSTR + 20 + j * 4];
            __half2* wd = (__half2*)&wb[r * K1_SSTR + 20 + j * 4];
            xd[0] = z2; xd[1] = z2;
            wd[0] = z2; wd[1] = z2;
        }
    }
    if (tid < 128) bs[tid] = b1[n0 + tid];
    __syncthreads();

    float acc[2][8][4];
#pragma unroll
    for (int mt = 0; mt < 2; mt++)
#pragma unroll
        for (int nt = 0; nt < 8; nt++)
#pragma unroll
            for (int j = 0; j < 4; j++) acc[mt][nt][j] = 0.0f;

#pragma unroll
    for (int ks = 0; ks < 2; ks++) {
        const int kc = ks * 16 + 2 * t;
        uint32_t af[2][4];
#pragma unroll
        for (int mt = 0; mt < 2; mt++) {
            const __half* ap = xa + (wm + mt * 16 + g) * K1_SSTR + kc;
            af[mt][0] = *(const uint32_t*)(ap);
            af[mt][1] = *(const uint32_t*)(ap + 8 * K1_SSTR);
            af[mt][2] = *(const uint32_t*)(ap + 8);
            af[mt][3] = *(const uint32_t*)(ap + 8 * K1_SSTR + 8);
        }
#pragma unroll
        for (int nt = 0; nt < 8; nt++) {
            const __half* bp = wb + (wn + nt * 8 + g) * K1_SSTR + kc;
            uint32_t bf[2];
            bf[0] = *(const uint32_t*)(bp);
            bf[1] = *(const uint32_t*)(bp + 8);
            mma16(acc[0][nt], af[0], bf);
            mma16(acc[1][nt], af[1], bf);
        }
    }

    // ---- staged output: 2 passes (mt), 64 rows x 128 cols each ----
    __half* stage = pool;   // 64 * ST_STR * 2 = 17408 B <= 20480 B pool
#pragma unroll
    for (int mt = 0; mt < 2; mt++) {
        __syncthreads();    // pool free (fragments consumed / prev pass read)
#pragma unroll
        for (int nt = 0; nt < 8; nt++) {
            const int col = wn + nt * 8 + t * 2;
            const float b0 = bs[col], b1v = bs[col + 1];
#pragma unroll
            for (int h = 0; h < 2; h++) {
                const int lrow = wmi * 16 + h * 8 + g;
                const float v0 = fmaxf(acc[mt][nt][h * 2 + 0] + b0, 0.0f);
                const float v1 = fmaxf(acc[mt][nt][h * 2 + 1] + b1v, 0.0f);
                *(__half2*)&stage[lrow * ST_STR + col] = __floats2half2_rn(v0, v1);
            }
        }
        __syncthreads();
        // coalesced uint4 stores: 64 rows x 16 chunks = 1024
#pragma unroll
        for (int i2 = 0; i2 < 4; i2++) {
            const int i = tid + i2 * 256;
            const int srow = i >> 4, chunk = i & 15;
            const int grow = m0 + (srow >> 4) * 32 + mt * 16 + (srow & 15);
            *(uint4*)&g_h[(size_t)grow * H1 + n0 + chunk * 8] =
                *(const uint4*)&stage[srow * ST_STR + chunk * 8];
        }
    }
}

// ---------------------------------------------------------------------------
// Kernel 2: persistent fp16 mma GEMM. BM=128, BN=128, BK=32, 4-stage
// cp.async. grid 296, block 256.
// ---------------------------------------------------------------------------
#define SSTRH    40
#define TILE_H   (128 * SSTRH)
#define STAGE_H  (2 * TILE_H)
#define STAGE_B  (STAGE_H * 2)
#define TILE_B   (TILE_H * 2)
#define K2_SMEM_BYTES (4 * STAGE_B)
#define NTILES   2048
#define K2_GRID  296

__global__ __launch_bounds__(256, 2) void k2_mma(
    const float* __restrict__ b21,  const float* __restrict__ bobs1,
    const float* __restrict__ W31,  const float* __restrict__ Wobs2)
{
    extern __shared__ __half smh[];
    __shared__ float ws[2][128];
    __shared__ float sred[2][128][2];

    const int tid  = threadIdx.x;
    const int wid  = tid >> 5;
    const int lane = tid & 31;
    const int g    = lane >> 2;
    const int t    = lane & 3;
    const int wm   = (wid & 3) * 32;
    const int wn   = (wid >> 2) * 64;
    const int half = wid >> 2;

    uint32_t smem_base;
    asm("{ .reg .u64 t; cvta.to.shared.u64 t, %1; cvt.u32.u64 %0, t; }"
        : "=r"(smem_base) : "l"(smh));

    const int lm = tid >> 2;
    const int lq = tid & 3;
    const uint32_t dOff = (uint32_t)(lm * SSTRH * 2 + lq * 16);

    const int lr  = lane & 7;
    const int sel = lane >> 3;
    uint32_t aOffL[2];
#pragma unroll
    for (int mt = 0; mt < 2; mt++)
        aOffL[mt] = (uint32_t)(((wm + mt * 16 + lr + (sel & 1) * 8) * SSTRH
                               + (sel >> 1) * 8) * 2);
    uint32_t bOffL[4];
#pragma unroll
    for (int np = 0; np < 4; np++)
        bOffL[np] = (uint32_t)(TILE_B + ((wn + np * 16 + lr + (sel >> 1) * 8) * SSTRH
                               + (sel & 1) * 8) * 2);

    for (int tile = blockIdx.x; tile < NTILES; tile += K2_GRID) {
        const int m0 = (tile >> 3) * 128;
        const int n0 = (tile & 7) * 128;
        const int pair = (n0 >= 512);

        const float* bsrc = pair ? (bobs1 + (n0 - 512)) : (b21 + n0);
        const float* w0g  = pair ? (Wobs2 + (n0 - 512)) : (W31 + n0);
        const float* w1g  = pair ? (Wobs2 + 512 + (n0 - 512)) : (W31 + 512 + n0);

        const __half* aG = &g_h [(size_t)(m0 + lm) * H1 + lq * 8];
        const __half* bG = &g_wh[(size_t)(n0 + lm) * H1 + lq * 8];

        float acc[2][8][4];
#pragma unroll
        for (int mt = 0; mt < 2; mt++)
#pragma unroll
            for (int nt = 0; nt < 8; nt++)
#pragma unroll
                for (int j = 0; j < 4; j++) acc[mt][nt][j] = 0.0f;

        // ---- prologue: stages 0..2 ----
#pragma unroll
        for (int p = 0; p < 3; p++) {
            const uint32_t aB = smem_base + p * STAGE_B + dOff;
            const uint32_t bB = aB + (uint32_t)TILE_B;
            const int k0 = p * 32;
#pragma unroll
            for (int i = 0; i < 2; i++) {
                cpa_cg(aB + i * 64 * SSTRH * 2, aG + (size_t)i * 64 * H1 + k0);
                cpa_ca(bB + i * 64 * SSTRH * 2, bG + (size_t)i * 64 * H1 + k0);
            }
            asm volatile("cp.async.commit_group;");
        }

        // ---- 32 slabs of BK=32 ----
        for (int s = 0; s < 32; s++) {
            const int stg = s & 3;
            asm volatile("cp.async.wait_group 2;");
            __syncthreads();

            if (s + 3 < 32) {
                const int pst = (s + 3) & 3;
                const uint32_t aB = smem_base + pst * STAGE_B + dOff;
                const uint32_t bB = aB + (uint32_t)TILE_B;
                const int k0 = (s + 3) * 32;
#pragma unroll
                for (int i = 0; i < 2; i++) {
                    cpa_cg(aB + i * 64 * SSTRH * 2, aG + (size_t)i * 64 * H1 + k0);
                    cpa_ca(bB + i * 64 * SSTRH * 2, bG + (size_t)i * 64 * H1 + k0);
                }
            }
            asm volatile("cp.async.commit_group;");

            {
                const uint32_t tb = smem_base + stg * STAGE_B;
#pragma unroll
                for (int ks = 0; ks < 2; ks++) {
                    const uint32_t kb = tb + ks * 32;
                    uint32_t af[2][4];
                    ldmx4(af[0], kb + aOffL[0]);
                    ldmx4(af[1], kb + aOffL[1]);
#pragma unroll
                    for (int np = 0; np < 4; np++) {
                        uint32_t bf[4];
                        ldmx4(bf, kb + bOffL[np]);
                        mma16(acc[0][2 * np + 0], af[0], bf);
                        mma16(acc[0][2 * np + 1], af[0], bf + 2);
                        mma16(acc[1][2 * np + 0], af[1], bf);
                        mma16(acc[1][2 * np + 1], af[1], bf + 2);
                    }
                }
            }
        }

        // ---- epilogue: relu + partial layer-3 dots ----
        if (tid < 128) ws[0][tid] = w0g[tid];
        else           ws[1][tid - 128] = w1g[tid - 128];
        __syncthreads();

        float u[4][2];
#pragma unroll
        for (int q = 0; q < 4; q++) { u[q][0] = 0.0f; u[q][1] = 0.0f; }

#pragma unroll
        for (int nt = 0; nt < 8; nt++) {
            const int col = wn + nt * 8 + t * 2;
            const float2 bb = *(const float2*)&bsrc[col];
            const float wa0 = ws[0][col], wa1 = ws[0][col + 1];
            const float wb0 = ws[1][col], wb1 = ws[1][col + 1];
#pragma unroll
            for (int q = 0; q < 4; q++) {
                const int mt = q >> 1, h = q & 1;
                const float v0 = fmaxf(acc[mt][nt][h * 2 + 0] + bb.x, 0.0f);
                const float v1 = fmaxf(acc[mt][nt][h * 2 + 1] + bb.y, 0.0f);
                u[q][0] = fmaf(v0, wa0, fmaf(v1, wa1, u[q][0]));
                u[q][1] = fmaf(v0, wb0, fmaf(v1, wb1, u[q][1]));
            }
        }

#pragma unroll
        for (int q = 0; q < 4; q++)
#pragma unroll
            for (int c = 0; c < 2; c++) {
                u[q][c] += __shfl_xor_sync(0xFFFFFFFFu, u[q][c], 1);
                u[q][c] += __shfl_xor_sync(0xFFFFFFFFu, u[q][c], 2);
            }

        if (t == 0) {
#pragma unroll
            for (int q = 0; q < 4; q++) {
                const int row = wm + (q >> 1) * 16 + (q & 1) * 8 + g;
                sred[half][row][0] = u[q][0];
                sred[half][row][1] = u[q][1];
            }
        }
        __syncthreads();

        {
            const int row = tid >> 1;
            const int c   = tid & 1;
            const float sum = sred[0][row][c] + sred[1][row][c];
            const int nb4 = tile & 3;
            g_part[(size_t)(m0 + row) * 16 + pair * 8 + nb4 * 2 + c] = sum;
        }
        __syncthreads();
    }
}

// ---------------------------------------------------------------------------
// Kernel 3: per-row partial sum + sigmoid + CBF epilogue. grid 128, block 256.
// ---------------------------------------------------------------------------
__global__ __launch_bounds__(256) void k3_final(
    const float* __restrict__ x,
    const float* __restrict__ mean_, const float* __restrict__ stdv,
    const float* __restrict__ b31,   const float* __restrict__ bobs2,
    float* __restrict__ out)
{
    const int row = blockIdx.x * 256 + threadIdx.x;

    const float* pp = &g_part[(size_t)row * 16];
    float4 pa = *(const float4*)&pp[0];
    float4 pb = *(const float4*)&pp[4];
    float4 pc = *(const float4*)&pp[8];
    float4 pd = *(const float4*)&pp[12];

    const float x31_0 = pa.x + pa.z + pb.x + pb.z + b31[0];
    const float x31_1 = pa.y + pa.w + pb.y + pb.w + b31[1];
    const float t0    = pc.x + pc.z + pd.x + pd.z + bobs2[0];
    const float t1    = pc.y + pc.w + pd.y + pd.w + bobs2[1];
    const float p0 = 4.0f / (1.0f + expf(-t0));
    const float p1 = 4.0f / (1.0f + expf(-t1));

    const float* xr = x + (size_t)row * NUM_IN;
    float x0v[NUM_IN];
#pragma unroll
    for (int c = 2; c < NUM_IN; c++) x0v[c] = fmaf(xr[c], stdv[c], mean_[c]);

    const float theta = x0v[2];
    const float v     = x0v[3];
    const float st = sinf(theta), ct = cosf(theta);
    const float ox = x0v[4], oy = x0v[5], oth = x0v[6], ov = x0v[7];
    const float dx = -ox, dy = -oy;
    const float ost = sinf(oth), oct = cosf(oth);
    const float R2 = 0.45f * 0.45f;

    const float barrier = dx * dx + dy * dy - R2;
    const float bdot    = 2.0f * dx * (v * ct - ov * oct)
                        + 2.0f * dy * (v * st - ov * ost);
    const float Lf2b    = 2.0f * (v * v + ov * ov
                        - 2.0f * v * ov * cosf(theta + oth));
    const float Gu1 = -2.0f * dx * v * st + 2.0f * dy * v * ct;
    const float Gu2 =  2.0f * dx * ct + 2.0f * dy * st;

    const float psum  = p0 + p1;
    const float pprod = p0 * p1;

    float o[14];
    o[0]  = x31_0;
    o[1]  = x31_1;
    o[2]  = -Gu1;
    o[3]  = -Gu2;
    o[10] = Lf2b + psum * bdot + pprod * barrier;

    const float sLf2b = 2.0f * v * v;
#pragma unroll
    for (int j = 0; j < 3; j++) {
        const float sdx = -x0v[8 + 4 * j];
        const float sdy = -x0v[9 + 4 * j];
        const float sb    = sdx * sdx + sdy * sdy - R2;
        const float sbdot = 2.0f * sdx * v * ct + 2.0f * sdy * v * st;
        const float sGu1  = -2.0f * sdx * v * st + 2.0f * sdy * v * ct;
        const float sGu2  =  2.0f * sdx * ct + 2.0f * sdy * st;
        o[4 + 2 * j] = -sGu1;
        o[5 + 2 * j] = -sGu2;
        o[11 + j]    = sLf2b + psum * sbdot + pprod * sb;
    }

    float* op = out + (size_t)row * 14;
#pragma unroll
    for (int i = 0; i < 14; i++) op[i] = o[i];
}

// ---------------------------------------------------------------------------
// Launch
// ---------------------------------------------------------------------------
extern "C" void kernel_launch(void* const* d_in, const int* in_sizes, int n_in,
                              void* d_out, int out_size)
{
    const float* x      = (const float*)d_in[0];
    const float* mean_  = (const float*)d_in[2];
    const float* stdv   = (const float*)d_in[3];
    const float* W1     = (const float*)d_in[4];
    const float* b1     = (const float*)d_in[5];
    const float* W21    = (const float*)d_in[6];
    const float* b21    = (const float*)d_in[7];
    const float* W31    = (const float*)d_in[8];
    const float* b31    = (const float*)d_in[9];
    const float* Wobs1  = (const float*)d_in[10];
    const float* bobs1  = (const float*)d_in[11];
    const float* Wobs2  = (const float*)d_in[12];
    const float* bobs2  = (const float*)d_in[13];
    float* out = (float*)d_out;

    cudaFuncSetAttribute(k2_mma, cudaFuncAttributeMaxDynamicSharedMemorySize,
                         K2_SMEM_BYTES);

    k01_l1_and_convert<<<3072, 256>>>(x, W1, b1, W21, Wobs1);
    k2_mma<<<K2_GRID, 256, K2_SMEM_BYTES>>>(b21, bobs1, W31, Wobs2);
    k3_final<<<B_ROWS / 256, 256>>>(x, mean_, stdv, b31, bobs2, out);
}